// round 5
// baseline (speedup 1.0000x reference)
#include <cuda_runtime.h>

// out[b, j] = prod_{i<=j} cos(params[i]) * cos(x[b, i])
// (RX/RY product state; CNOT chain => prefix-XOR => prefix product of <Z>.)
//
// One thread per OUTPUT ELEMENT. Each warp handles 3 rows (segments of 10
// lanes; lanes 30,31 idle). Warp-level segmented inclusive product scan via
// __shfl_up_sync gives the prefix in 4 steps. 163,840 threads => ~35 warps/SM
// of latency hiding, vs 2 warps/SM before.

#define N_WIRES 10
#define ROWS_PER_WARP 3

__global__ void __launch_bounds__(256)
qgate_kernel(const float* __restrict__ x,
             const float* __restrict__ params,
             float* __restrict__ out,
             int B)
{
    int gtid = blockIdx.x * blockDim.x + threadIdx.x;
    int warp = gtid >> 5;
    int lane = threadIdx.x & 31;
    int seg  = lane / N_WIRES;           // 0..2 useful, 3 = idle lanes
    int col  = lane - seg * N_WIRES;     // position within row
    int row  = warp * ROWS_PER_WARP + seg;

    bool active = (seg < ROWS_PER_WARP) && (row < B);

    float v = 1.0f;
    if (active) {
        float xe = __ldg(&x[row * N_WIRES + col]);       // coalesced 32b
        v = __cosf(params[col]) * __cosf(xe);            // params: L1 broadcast
    }

    // Segmented inclusive product scan (segments of N_WIRES lanes).
    // col >= d guarantees the source lane is in the same segment.
#pragma unroll
    for (int d = 1; d < N_WIRES; d <<= 1) {
        float up = __shfl_up_sync(0xFFFFFFFFu, v, d);
        if (col >= d) v *= up;
    }

    if (active) out[row * N_WIRES + col] = v;
}

extern "C" void kernel_launch(void* const* d_in, const int* in_sizes, int n_in,
                              void* d_out, int out_size)
{
    const float* x      = (const float*)d_in[0];   // (B, 10) float32
    const float* params = (const float*)d_in[1];   // (10,)  float32
    float* out          = (float*)d_out;           // (B, 10) float32

    int B = in_sizes[0] / N_WIRES;                      // 16384
    int warps   = (B + ROWS_PER_WARP - 1) / ROWS_PER_WARP;  // 5462
    int threads = 256;                                   // 8 warps/block
    int blocks  = (warps * 32 + threads - 1) / threads;  // 683
    qgate_kernel<<<blocks, threads>>>(x, params, out, B);
}